// round 1
// baseline (speedup 1.0000x reference)
#include <cuda_runtime.h>
#include <math.h>

// Problem constants
#define BB   64
#define TT   64
#define QQ   4
#define SSS  4
#define HH   192
#define DIN  188
#define NACT 576
#define GT   256            // Q*S*Q*S tile
#define NGAMMA ((size_t)BB*TT*TT*GT)   // 67,108,864

// d_out layout (float32, concat of outputs in return order)
#define OFF_H 0                                   // 64*192 = 12288
#define OFF_G ((size_t)(BB*HH))                   // gamma: 67,108,864
#define OFF_A (OFF_G + NGAMMA)                    // alpha: 64*64*16 = 65536
#define OFF_O (OFF_A + (size_t)BB*TT*QQ*SSS)      // obs: 256

// Scratch (no allocations allowed)
__device__ float g_actions[BB * NACT];            // softmax outputs
__device__ float g_tmp[BB * TT * 64];             // tmp[b,k,u,y,r]

// ---------------------------------------------------------------------------
// K0: h_new = tanh([x, top_stack] @ W_ih^T + b_ih + h @ W_hh^T + b_hh)
// grid=B, block=192 (one thread per output unit)
// ---------------------------------------------------------------------------
__global__ void k_rnn(const float* __restrict__ x, const float* __restrict__ h,
                      const float* __restrict__ top,
                      const float* __restrict__ Wih, const float* __restrict__ bih,
                      const float* __restrict__ Whh, const float* __restrict__ bhh,
                      float* __restrict__ out_h) {
    int b = blockIdx.x;
    int j = threadIdx.x;            // 0..191
    __shared__ float xin[HH];
    __shared__ float hs[HH];
    if (j < DIN) xin[j] = x[b * DIN + j];
    else         xin[j] = top[b * SSS + (j - DIN)];
    hs[j] = h[b * HH + j];
    __syncthreads();
    const float* wi = Wih + j * HH; // W_ih row length = DIN+S = 192
    const float* wh = Whh + j * HH;
    float acc = bih[j] + bhh[j];
#pragma unroll 8
    for (int d = 0; d < HH; d++) acc += xin[d] * wi[d] + hs[d] * wh[d];
    out_h[b * HH + j] = tanhf(acc);
}

// ---------------------------------------------------------------------------
// K1: actions = softmax(h_new @ W_lin^T + b_lin)
// grid=B, block=576 (one thread per logit)
// ---------------------------------------------------------------------------
__global__ void k_act(const float* __restrict__ hnew,
                      const float* __restrict__ Wlin, const float* __restrict__ blin) {
    int b = blockIdx.x;
    int n = threadIdx.x;            // 0..575
    __shared__ float hs[HH];
    __shared__ float red[32];
    if (n < HH) hs[n] = hnew[b * HH + n];
    __syncthreads();
    const float* w = Wlin + n * HH;
    float acc = blin[n];
#pragma unroll 8
    for (int d = 0; d < HH; d++) acc += hs[d] * w[d];

    int wid = n >> 5, lid = n & 31;
    // block max
    float v = acc;
    for (int o = 16; o > 0; o >>= 1) v = fmaxf(v, __shfl_xor_sync(0xffffffffu, v, o));
    if (lid == 0) red[wid] = v;
    __syncthreads();
    if (n == 0) {
        float m = red[0];
        for (int i = 1; i < 18; i++) m = fmaxf(m, red[i]);
        red[0] = m;
    }
    __syncthreads();
    float mx = red[0];
    float e = expf(acc - mx);
    __syncthreads();                // done reading red[0] as max
    // block sum
    v = e;
    for (int o = 16; o > 0; o >>= 1) v += __shfl_xor_sync(0xffffffffu, v, o);
    if (lid == 0) red[wid] = v;
    __syncthreads();
    if (n == 0) {
        float s = 0.f;
        for (int i = 0; i < 18; i++) s += red[i];
        red[0] = s;
    }
    __syncthreads();
    g_actions[b * NACT + n] = e / red[0];
}

// ---------------------------------------------------------------------------
// K2: tmp[b,k,u,y,r] = sum_{s,z} gamma[b,k,ts-1,u,y,s,z] * pop[b,s,z,r]
// grid=(T,B), block=64 (thread = uy*4+r)
// ---------------------------------------------------------------------------
__global__ void k_tmp(const float* __restrict__ gamma, const int* __restrict__ tstep) {
    int k = blockIdx.x, b = blockIdx.y;
    int ts = tstep[0] + 1;
    int tid = threadIdx.x;          // 0..63
    __shared__ float g[GT];
    __shared__ float p[64];
    const float* gc = gamma + (((size_t)(b * TT + k)) * TT + (ts - 1)) * GT;
    for (int i = tid; i < GT; i += 64) g[i] = gc[i];
    p[tid] = g_actions[b * NACT + 256 + tid];   // pop[b, s,z,r] at tid = sz*4+r
    __syncthreads();
    int uy = tid >> 2, r = tid & 3;
    float acc = 0.f;
#pragma unroll
    for (int sz = 0; sz < 16; sz++) acc += g[uy * 16 + sz] * p[sz * 4 + r];
    g_tmp[(b * TT + k) * 64 + tid] = acc;
}

// ---------------------------------------------------------------------------
// K3: gamma_t[b,i,q,x,r,y] = push_t + pop_t + repl_t  -> d_out gamma column ts
// grid=(T,B), block=256 (thread tid = qx*16 + ry, matching output layout)
// ---------------------------------------------------------------------------
__global__ void k_gamma(const float* __restrict__ gamma, const int* __restrict__ tstep,
                        float* __restrict__ d_out) {
    int i = blockIdx.x, b = blockIdx.y;
    int ts = tstep[0] + 1;
    int tid = threadIdx.x;          // 0..255
    int qx = tid >> 4, ry = tid & 15, r = ry >> 2, y = ry & 3;
    __shared__ float gcol[GT];      // gamma[b,i,ts-1] as [qx, sz]
    __shared__ float repl[GT];      // repl[b] as [sz, ry]
    __shared__ float gbuf[2][GT];
    __shared__ float tbuf[2][64];

    size_t base_bi = (size_t)(b * TT + i) * TT;
    gcol[tid] = gamma[(base_bi + (ts - 1)) * GT + tid];
    repl[tid] = g_actions[b * NACT + 320 + tid];
    __syncthreads();

    // repl_t
    float acc = 0.f;
#pragma unroll
    for (int sz = 0; sz < 16; sz++) acc += gcol[qx * 16 + sz] * repl[sz * 16 + ry];
    // push_t (only row i == ts-1)
    if (i == ts - 1) acc += g_actions[b * NACT + tid];

    // pop_t: sum over k in (i, ts-1)
    int k0 = i + 1, k1 = ts - 1;    // k in [k0, k1)
    if (k0 < k1) {
        gbuf[0][tid] = gamma[(base_bi + k0) * GT + tid];
        if (tid < 64) tbuf[0][tid] = g_tmp[(b * TT + k0) * 64 + tid];
    }
    int buf = 0;
    for (int k = k0; k < k1; k++) {
        __syncthreads();            // gbuf[buf]/tbuf[buf] ready
        int nb = buf ^ 1;
        if (k + 1 < k1) {
            gbuf[nb][tid] = gamma[(base_bi + k + 1) * GT + tid];
            if (tid < 64) tbuf[nb][tid] = g_tmp[(b * TT + k + 1) * 64 + tid];
        }
        float a0 = 0.f;
#pragma unroll
        for (int u = 0; u < 4; u++)
            a0 += gbuf[buf][qx * 16 + u * 4 + y] * tbuf[buf][(u * 4 + y) * 4 + r];
        acc += a0;
        buf = nb;
    }

    d_out[OFF_G + (base_bi + ts) * GT + tid] = acc;
}

// ---------------------------------------------------------------------------
// K4: new_alpha (copy + row ts = alpha_t), obs
// grid=B, block=64 (thread = i for the reduction)
// alpha_t[b,r,y] = sum_{i,q,x} alpha[b,i,q,x] * gamma_t[b,i,q,x,r,y]
// ---------------------------------------------------------------------------
__global__ void k_alpha(const float* __restrict__ alpha, const int* __restrict__ tstep,
                        float* __restrict__ d_out) {
    int b = blockIdx.x;
    int tid = threadIdx.x;          // 0..63
    int ts = tstep[0] + 1;
    float* na = d_out + OFF_A + (size_t)b * TT * 16;
    const float* a_in = alpha + (size_t)b * TT * 16;

    // copy alpha rows except ts
    for (int idx = tid; idx < TT * 16; idx += 64) {
        if ((idx >> 4) != ts) na[idx] = a_in[idx];
    }

    // per-thread partial over i = tid
    const float* gt = d_out + OFF_G + ((size_t)(b * TT + tid) * TT + ts) * GT;
    float part[16];
#pragma unroll
    for (int j = 0; j < 16; j++) part[j] = 0.f;
    for (int qx = 0; qx < 16; qx++) {
        float a = a_in[tid * 16 + qx];
#pragma unroll
        for (int j = 0; j < 16; j++) part[j] += a * gt[qx * 16 + j];
    }
    __shared__ float red[64 * 16];
#pragma unroll
    for (int j = 0; j < 16; j++) red[tid * 16 + j] = part[j];
    __syncthreads();
    if (tid < 16) {
        float s = 0.f;
        for (int t = 0; t < 64; t++) s += red[t * 16 + tid];
        na[ts * 16 + tid] = s;      // new_alpha row ts
        red[tid] = s;               // each thread touches only its own slot (t=0 of its column)
    }
    __syncthreads();
    if (tid < 4) {                  // obs[b,y] = sum_r at[r,y] / (sum_all + 1e-5)
        float total = 0.f;
        for (int j = 0; j < 16; j++) total += red[j];
        float sy = red[tid] + red[4 + tid] + red[8 + tid] + red[12 + tid];
        d_out[OFF_O + b * SSS + tid] = sy / (total + 1e-5f);
    }
}

// ---------------------------------------------------------------------------
// K5: bulk copy gamma -> d_out gamma region, skipping column ts (written by K3)
// ---------------------------------------------------------------------------
__global__ void k_copy(const float4* __restrict__ gin, const int* __restrict__ tstep,
                       float4* __restrict__ gout) {
    int ts = tstep[0] + 1;
    const size_t N4 = NGAMMA / 4;   // 16,777,216
    size_t idx = (size_t)blockIdx.x * blockDim.x + threadIdx.x;
    size_t stride = (size_t)gridDim.x * blockDim.x;
    for (size_t i = idx; i < N4; i += stride) {
        int k = (int)((i >> 6) & 63);   // 64 float4 per (b,i,k) tile
        if (k != ts) gout[i] = gin[i];
    }
}

// ---------------------------------------------------------------------------
extern "C" void kernel_launch(void* const* d_in, const int* in_sizes, int n_in,
                              void* d_out, int out_size) {
    const float* x      = (const float*)d_in[0];
    const float* h      = (const float*)d_in[1];
    const float* gamma  = (const float*)d_in[2];
    const float* alpha  = (const float*)d_in[3];
    const float* top    = (const float*)d_in[4];
    const float* Wih    = (const float*)d_in[5];
    const float* bih    = (const float*)d_in[6];
    const float* Whh    = (const float*)d_in[7];
    const float* bhh    = (const float*)d_in[8];
    const float* Wlin   = (const float*)d_in[9];
    const float* blin   = (const float*)d_in[10];
    const int*   tstep  = (const int*)d_in[11];
    float* out = (float*)d_out;

    k_rnn<<<BB, HH>>>(x, h, top, Wih, bih, Whh, bhh, out + OFF_H);
    k_act<<<BB, NACT>>>(out + OFF_H, Wlin, blin);
    k_tmp<<<dim3(TT, BB), 64>>>(gamma, tstep);
    k_gamma<<<dim3(TT, BB), 256>>>(gamma, tstep, out);
    k_alpha<<<BB, 64>>>(alpha, tstep, out);
    k_copy<<<4736, 256>>>((const float4*)gamma, tstep, (float4*)(out + OFF_G));
}

// round 2
// speedup vs baseline: 1.3415x; 1.3415x over previous
#include <cuda_runtime.h>
#include <math.h>

// Problem constants
#define BB   64
#define TT   64
#define QQ   4
#define SSS  4
#define HH   192
#define DIN  188
#define NACT 576
#define GT   256            // Q*S*Q*S tile
#define NGAMMA ((size_t)BB*TT*TT*GT)   // 67,108,864 floats = 256 MB

// d_out layout (float32, concat of outputs in return order)
#define OFF_H 0
#define OFF_G ((size_t)(BB*HH))
#define OFF_A (OFF_G + NGAMMA)
#define OFF_O (OFF_A + (size_t)BB*TT*QQ*SSS)

// Scratch (no allocations allowed)
__device__ float g_actions[BB * NACT];
__device__ float g_tmp[BB * TT * 64];             // tmp[b,k,u,y,r]

__device__ __forceinline__ float warp_sum(float v) {
#pragma unroll
    for (int o = 16; o > 0; o >>= 1) v += __shfl_xor_sync(0xffffffffu, v, o);
    return v;
}

// ---------------------------------------------------------------------------
// K0: h_new = tanh([x, top] @ W_ih^T + b_ih + h @ W_hh^T + b_hh)
// grid=B, block=192 (6 warps). Warp w computes outputs j = w*32..w*32+31.
// Lanes stride the dot dimension -> coalesced weight loads.
// ---------------------------------------------------------------------------
__global__ void k_rnn(const float* __restrict__ x, const float* __restrict__ h,
                      const float* __restrict__ top,
                      const float* __restrict__ Wih, const float* __restrict__ bih,
                      const float* __restrict__ Whh, const float* __restrict__ bhh,
                      float* __restrict__ out_h) {
    int b = blockIdx.x;
    int tid = threadIdx.x;
    int w = tid >> 5, l = tid & 31;
    __shared__ float xin[HH];
    __shared__ float hs[HH];
    if (tid < DIN) xin[tid] = x[b * DIN + tid];
    else           xin[tid] = top[b * SSS + (tid - DIN)];
    hs[tid] = h[b * HH + tid];
    __syncthreads();

#pragma unroll 4
    for (int c = 0; c < 32; c++) {
        int j = w * 32 + c;
        const float* wi = Wih + j * HH;
        const float* wh = Whh + j * HH;
        float acc = 0.f;
#pragma unroll
        for (int m = 0; m < 6; m++) {
            int d = l + 32 * m;
            acc += xin[d] * wi[d] + hs[d] * wh[d];
        }
        acc = warp_sum(acc);
        if (l == 0) out_h[b * HH + j] = tanhf(acc + bih[j] + bhh[j]);
    }
}

// ---------------------------------------------------------------------------
// K1: actions = softmax(h_new @ W_lin^T + b_lin)
// grid=B, block=256 (8 warps). Warp w computes logits n = w*72..w*72+71,
// lanes stride d (coalesced). Then block-wide softmax over 576.
// ---------------------------------------------------------------------------
__global__ void k_act(const float* __restrict__ hnew,
                      const float* __restrict__ Wlin, const float* __restrict__ blin) {
    int b = blockIdx.x;
    int tid = threadIdx.x;
    int w = tid >> 5, l = tid & 31;
    __shared__ float hs[HH];
    __shared__ float logit[NACT];
    __shared__ float red[8];
    if (tid < HH) hs[tid] = hnew[b * HH + tid];
    __syncthreads();

    for (int t = 0; t < 72; t++) {
        int n = w * 72 + t;
        const float* wr = Wlin + n * HH;
        float acc = 0.f;
#pragma unroll
        for (int m = 0; m < 6; m++) {
            int d = l + 32 * m;
            acc += hs[d] * wr[d];
        }
        acc = warp_sum(acc);
        if (l == 0) logit[n] = acc + blin[n];
    }
    __syncthreads();

    // block max
    float lm = -1e30f;
    for (int n = tid; n < NACT; n += 256) lm = fmaxf(lm, logit[n]);
#pragma unroll
    for (int o = 16; o > 0; o >>= 1) lm = fmaxf(lm, __shfl_xor_sync(0xffffffffu, lm, o));
    if (l == 0) red[w] = lm;
    __syncthreads();
    float mx = red[0];
#pragma unroll
    for (int i = 1; i < 8; i++) mx = fmaxf(mx, red[i]);

    // exp + block sum
    float ls = 0.f;
    float ev[3];
    int cnt = 0;
    for (int n = tid; n < NACT; n += 256) {
        float e = expf(logit[n] - mx);
        ev[cnt++] = e;
        ls += e;
    }
    ls = warp_sum(ls);
    __syncthreads();
    if (l == 0) red[w] = ls;
    __syncthreads();
    float s = 0.f;
#pragma unroll
    for (int i = 0; i < 8; i++) s += red[i];
    float inv = 1.0f / s;
    cnt = 0;
    for (int n = tid; n < NACT; n += 256) g_actions[b * NACT + n] = ev[cnt++] * inv;
}

// ---------------------------------------------------------------------------
// K2: tmp[b,k,u,y,r] = sum_{s,z} gamma[b,k,ts-1,u,y,s,z] * pop[b,s,z,r]
// grid=(T,B), block=64
// ---------------------------------------------------------------------------
__global__ void k_tmp(const float* __restrict__ gamma, const int* __restrict__ tstep) {
    int k = blockIdx.x, b = blockIdx.y;
    int ts = tstep[0] + 1;
    int tid = threadIdx.x;
    __shared__ float g[GT];
    __shared__ float p[64];
    const float* gc = gamma + (((size_t)(b * TT + k)) * TT + (ts - 1)) * GT;
    for (int i = tid; i < GT; i += 64) g[i] = gc[i];
    p[tid] = g_actions[b * NACT + 256 + tid];   // pop[b, s,z,r] at tid = sz*4+r
    __syncthreads();
    int uy = tid >> 2, r = tid & 3;
    float acc = 0.f;
#pragma unroll
    for (int sz = 0; sz < 16; sz++) acc += g[uy * 16 + sz] * p[sz * 4 + r];
    g_tmp[(b * TT + k) * 64 + tid] = acc;
}

// ---------------------------------------------------------------------------
// K3: gamma_t = push_t + pop_t + repl_t -> d_out gamma column ts
// grid=(T,B), block=256. 4 k-slices batched per barrier stage (MLP=4).
// ---------------------------------------------------------------------------
__global__ void k_gamma(const float* __restrict__ gamma, const int* __restrict__ tstep,
                        float* __restrict__ d_out) {
    int i = blockIdx.x, b = blockIdx.y;
    int ts = tstep[0] + 1;
    int tid = threadIdx.x;
    int qx = tid >> 4, ry = tid & 15, r = ry >> 2, y = ry & 3;
    __shared__ float gcol[GT];
    __shared__ float repl[GT];
    __shared__ float gbuf[4][GT];
    __shared__ float tbuf[4][64];

    size_t base_bi = (size_t)(b * TT + i) * TT;
    gcol[tid] = gamma[(base_bi + (ts - 1)) * GT + tid];
    repl[tid] = g_actions[b * NACT + 320 + tid];
    __syncthreads();

    float acc = 0.f;
#pragma unroll
    for (int sz = 0; sz < 16; sz++) acc += gcol[qx * 16 + sz] * repl[sz * 16 + ry];
    if (i == ts - 1) acc += g_actions[b * NACT + tid];

    int k0 = i + 1, k1 = ts - 1;    // k in [k0, k1)
    for (int kb = k0; kb < k1; kb += 4) {
        __syncthreads();            // previous stage compute done
#pragma unroll
        for (int j = 0; j < 4; j++)
            if (kb + j < k1) gbuf[j][tid] = gamma[(base_bi + kb + j) * GT + tid];
        {
            int j = tid >> 6, e = tid & 63;
            if (kb + j < k1) tbuf[j][e] = g_tmp[(b * TT + kb + j) * 64 + e];
        }
        __syncthreads();
#pragma unroll
        for (int j = 0; j < 4; j++) {
            if (kb + j < k1) {
#pragma unroll
                for (int u = 0; u < 4; u++)
                    acc += gbuf[j][qx * 16 + u * 4 + y] * tbuf[j][(u * 4 + y) * 4 + r];
            }
        }
    }

    d_out[OFF_G + (base_bi + ts) * GT + tid] = acc;
}

// ---------------------------------------------------------------------------
// K4: new_alpha (copy + row ts = alpha_t), obs
// grid=B, block=256 (8 warps). Warp w handles i = w, w+8, ...
// Coalesced gamma_t reads; ry = lane&15 is invariant under +32 strides.
// ---------------------------------------------------------------------------
__global__ void k_alpha(const float* __restrict__ alpha, const int* __restrict__ tstep,
                        float* __restrict__ d_out) {
    int b = blockIdx.x;
    int tid = threadIdx.x;
    int w = tid >> 5, l = tid & 31;
    int ts = tstep[0] + 1;
    float* na = d_out + OFF_A + (size_t)b * TT * 16;
    const float* a_in = alpha + (size_t)b * TT * 16;

    for (int idx = tid; idx < TT * 16; idx += 256) {
        if ((idx >> 4) != ts) na[idx] = a_in[idx];
    }

    float part = 0.f;   // partial for ry = l & 15
    for (int i = w; i < TT; i += 8) {
        const float* gt = d_out + OFF_G + (((size_t)(b * TT + i)) * TT + ts) * GT;
        const float* ar = a_in + i * 16;
#pragma unroll
        for (int m = 0; m < 8; m++) {
            int e = l + 32 * m;
            part += ar[e >> 4] * gt[e];
        }
    }
    part += __shfl_down_sync(0xffffffffu, part, 16);
    __shared__ float red[8][16];
    if (l < 16) red[w][l] = part;
    __syncthreads();
    __shared__ float s16[16];
    if (tid < 16) {
        float s = 0.f;
#pragma unroll
        for (int ww = 0; ww < 8; ww++) s += red[ww][tid];
        na[ts * 16 + tid] = s;
        s16[tid] = s;
    }
    __syncthreads();
    if (tid < 4) {
        float total = 0.f;
#pragma unroll
        for (int j = 0; j < 16; j++) total += s16[j];
        float sy = s16[tid] + s16[4 + tid] + s16[8 + tid] + s16[12 + tid];
        d_out[OFF_O + b * SSS + tid] = sy / (total + 1e-5f);
    }
}

// ---------------------------------------------------------------------------
extern "C" void kernel_launch(void* const* d_in, const int* in_sizes, int n_in,
                              void* d_out, int out_size) {
    const float* x      = (const float*)d_in[0];
    const float* h      = (const float*)d_in[1];
    const float* gamma  = (const float*)d_in[2];
    const float* alpha  = (const float*)d_in[3];
    const float* top    = (const float*)d_in[4];
    const float* Wih    = (const float*)d_in[5];
    const float* bih    = (const float*)d_in[6];
    const float* Whh    = (const float*)d_in[7];
    const float* bhh    = (const float*)d_in[8];
    const float* Wlin   = (const float*)d_in[9];
    const float* blin   = (const float*)d_in[10];
    const int*   tstep  = (const int*)d_in[11];
    float* out = (float*)d_out;

    // Bulk gamma copy (stale column ts gets overwritten by k_gamma below).
    cudaMemcpyAsync(out + OFF_G, gamma, NGAMMA * sizeof(float),
                    cudaMemcpyDeviceToDevice);

    k_rnn<<<BB, HH>>>(x, h, top, Wih, bih, Whh, bhh, out + OFF_H);
    k_act<<<BB, 256>>>(out + OFF_H, Wlin, blin);
    k_tmp<<<dim3(TT, BB), 64>>>(gamma, tstep);
    k_gamma<<<dim3(TT, BB), 256>>>(gamma, tstep, out);
    k_alpha<<<BB, 256>>>(alpha, tstep, out);
}